// round 14
// baseline (speedup 1.0000x reference)
#include <cuda_runtime.h>
#include <cuda_bf16.h>
#include <math.h>

// B=8, D=64, T=512, O=256 (fixed by the reference)
#define PB 8
#define PD 64
#define PT 512
#define PO 256
#define NK 28              // branch-2 Taylor terms (center 0.5, |z*dt| <= 6.93)
#define NK1 10             // branch-1 Taylor terms (|z*dt| <= 0.693)
#define T0 0.5f
#define THREADS 256
#define TH 256             // t-points per block (T/2)

// Cross-block moment slots (already scaled by 1/k!): [t-half][bd][k]
__device__ float2 g_m1[2][PB * PD][NK1];
__device__ float2 g_m2[2][PB * PD][NK];
__device__ unsigned g_tick[PB * PD];

__device__ __forceinline__ float ex2a(float x) {
    float y; asm("ex2.approx.ftz.f32 %0, %1;" : "=f"(y) : "f"(x)); return y;
}
__device__ __forceinline__ float lg2a(float x) {
    float y; asm("lg2.approx.ftz.f32 %0, %1;" : "=f"(y) : "f"(x)); return y;
}
__device__ __forceinline__ float wred(float v) {
    v += __shfl_xor_sync(0xffffffffu, v, 16);
    v += __shfl_xor_sync(0xffffffffu, v, 8);
    v += __shfl_xor_sync(0xffffffffu, v, 4);
    v += __shfl_xor_sync(0xffffffffu, v, 2);
    v += __shfl_xor_sync(0xffffffffu, v, 1);
    return v;
}

__constant__ float inv_fact[NK] = {
    1.0f,           1.0f,           5.0e-1f,        1.6666667e-1f,
    4.1666667e-2f,  8.3333333e-3f,  1.3888889e-3f,  1.9841270e-4f,
    2.4801587e-5f,  2.7557319e-6f,  2.7557319e-7f,  2.5052108e-8f,
    2.0876757e-9f,  1.6059044e-10f, 1.1470746e-11f, 7.6471637e-13f,
    4.7794773e-14f, 2.8114573e-15f, 1.5619207e-16f, 8.2206352e-18f,
    4.1103176e-19f, 1.9572941e-20f, 8.8967914e-22f, 3.8681702e-23f,
    1.6117376e-24f, 6.4469503e-26f, 2.4795963e-27f, 9.1836899e-29f
};

__global__ __launch_bounds__(THREADS, 4)
void interp_kernel(const float* __restrict__ x,
                   const float* __restrict__ grid,
                   const float* __restrict__ kern,
                   float* __restrict__ out) {
    // 1024 blocks: (b, d, t-half). Second arriver per (b,d) combines + evals.
    const int bid = blockIdx.x;
    const int h   = bid & 1;
    const int bd  = bid >> 1;
    const int d   = bd & (PD - 1);
    const int b   = bd >> 6;
    const int tid  = threadIdx.x;
    const int lane = tid & 31;
    const int wid  = tid >> 5;

    __shared__ __align__(16) float4 sPw[TH];    // {dt, dt2, dt4, dt8}
    __shared__ __align__(16) float4 sU[TH];     // {u1, u1*v, u2, u2*v}
    __shared__ __align__(8)  float2 sM1[NK1];   // {S1w, S1y}[k] / k!
    __shared__ __align__(8)  float2 sM2[NK];    // {S2w, S2y}[k] / k!
    __shared__ int s_last;

    const size_t xoff = (size_t)(b * 3 * PD + d) * PT + h * TH;
    const float* vp = x + xoff;
    const float* mp = x + xoff + (size_t)PD * PT;
    const float* tp = x + xoff + (size_t)(2 * PD) * PT;

    const float k0 = kern[d];
    const float alpha = (k0 > 20.0f) ? k0 : log1pf(__expf(k0));
    const float c1 = -alpha * 1.4426950408889634f;   // -alpha*log2(e)

    // ---- Phase A0: per-t weights + power ladder (mask is exactly 0/1) ----
    {
        const float tv = tp[tid];
        const float mv = mp[tid];
        const float vv = vp[tid];
        float u1 = ex2a(c1 * tv * tv);           // e^{-alpha t^2}
        if (mv < 0.5f) u1 = 0.0f;
        const float p2 = u1 * u1;
        const float p4 = p2 * p2;
        const float p8 = p4 * p4;
        const float u2 = p8 * p2;                // u1^10
        const float dt  = tv - T0;
        const float dt2 = dt * dt;
        const float dt4 = dt2 * dt2;
        sPw[tid] = make_float4(dt, dt2, dt4, dt4 * dt4);
        sU[tid]  = make_float4(u1, u1 * vv, u2, u2 * vv);
    }
    __syncthreads();

    // ---- Phase A: warp w owns S2 ks {w, w+8, w+16, w+24<28},
    //               S1 ks {w, w+8<10} ----
    float s1a0=0,s1a1=0, s1b0=0,s1b1=0;
    float s2a0=0,s2a1=0, s2b0=0,s2b1=0, s2c0=0,s2c1=0, s2d0=0,s2d1=0;

    #pragma unroll 2
    for (int c = 0; c < TH / 32; c++) {
        const int t = c * 32 + lane;
        const float4 P = sPw[t];
        const float4 U = sU[t];
        float pw0 = 1.0f;                        // dt^wid (wid uniform per warp)
        if (wid & 1) pw0 *= P.x;
        if (wid & 2) pw0 *= P.y;
        if (wid & 4) pw0 *= P.z;
        s1a0 = __fmaf_rn(U.x, pw0, s1a0); s1a1 = __fmaf_rn(U.y, pw0, s1a1);
        s2a0 = __fmaf_rn(U.z, pw0, s2a0); s2a1 = __fmaf_rn(U.w, pw0, s2a1);
        const float pw1 = pw0 * P.w;
        if (wid < 2) {
            s1b0 = __fmaf_rn(U.x, pw1, s1b0); s1b1 = __fmaf_rn(U.y, pw1, s1b1);
        }
        s2b0 = __fmaf_rn(U.z, pw1, s2b0); s2b1 = __fmaf_rn(U.w, pw1, s2b1);
        const float pw2 = pw1 * P.w;
        s2c0 = __fmaf_rn(U.z, pw2, s2c0); s2c1 = __fmaf_rn(U.w, pw2, s2c1);
        if (wid < 4) {
            const float pw3 = pw2 * P.w;
            s2d0 = __fmaf_rn(U.z, pw3, s2d0); s2d1 = __fmaf_rn(U.w, pw3, s2d1);
        }
    }

    s1a0 = wred(s1a0); s1a1 = wred(s1a1);
    s2a0 = wred(s2a0); s2a1 = wred(s2a1);
    s2b0 = wred(s2b0); s2b1 = wred(s2b1);
    s2c0 = wred(s2c0); s2c1 = wred(s2c1);
    if (wid < 2) { s1b0 = wred(s1b0); s1b1 = wred(s1b1); }
    if (wid < 4) { s2d0 = wred(s2d0); s2d1 = wred(s2d1); }

    if (lane == 0) {
        float f; float2 m;
        f = inv_fact[wid];      m = make_float2(s1a0*f, s1a1*f);
        sM1[wid] = m;      g_m1[h][bd][wid] = m;
        f = inv_fact[wid];      m = make_float2(s2a0*f, s2a1*f);
        sM2[wid] = m;      g_m2[h][bd][wid] = m;
        f = inv_fact[wid + 8];  m = make_float2(s2b0*f, s2b1*f);
        sM2[wid + 8] = m;  g_m2[h][bd][wid + 8] = m;
        f = inv_fact[wid + 16]; m = make_float2(s2c0*f, s2c1*f);
        sM2[wid + 16] = m; g_m2[h][bd][wid + 16] = m;
        if (wid < 2) {
            f = inv_fact[wid + 8]; m = make_float2(s1b0*f, s1b1*f);
            sM1[wid + 8] = m;  g_m1[h][bd][wid + 8] = m;
        }
        if (wid < 4) {
            f = inv_fact[wid + 24]; m = make_float2(s2d0*f, s2d1*f);
            sM2[wid + 24] = m; g_m2[h][bd][wid + 24] = m;
        }
    }

    // ---- Ticket: the second arriver combines + evaluates ----
    __threadfence();
    __syncthreads();
    if (tid == 0)
        s_last = (atomicAdd(&g_tick[bd], 1u) == 1u);
    __syncthreads();
    if (!s_last) return;

    if (tid < NK1) {
        const float2 p = __ldcg(&g_m1[1 - h][bd][tid]);
        float2 m = sM1[tid];
        m.x += p.x; m.y += p.y;
        sM1[tid] = m;
    } else if (tid < NK1 + NK) {
        const int k = tid - NK1;
        const float2 p = __ldcg(&g_m2[1 - h][bd][k]);
        float2 m = sM2[k];
        m.x += p.x; m.y += p.y;
        sM2[k] = m;
    } else if (tid == NK1 + NK) {
        g_tick[bd] = 0u;                // reset for next graph replay
    }
    __syncthreads();

    // ---- Phase B: per-output Horner evaluation ----
    const int o = tid;
    const float g = grid[b * PO + o];
    const float z1 = 2.0f * alpha * g;       // beta1 * g
    const float z2 = 20.0f * alpha * g;      // beta2 * g

    float f2w = 0.0f, f2y = 0.0f;
    #pragma unroll
    for (int k = NK - 1; k >= 0; k--) {
        const float2 M = sM2[k];
        f2w = __fmaf_rn(f2w, z2, M.x);
        f2y = __fmaf_rn(f2y, z2, M.y);
    }
    float f1w = 0.0f, f1y = 0.0f;
    #pragma unroll
    for (int k = NK1 - 1; k >= 0; k--) {
        const float2 M = sM1[k];
        f1w = __fmaf_rn(f1w, z1, M.x);
        f1y = __fmaf_rn(f1y, z1, M.y);
    }

    // w = ln(S1w) + alpha*g*(1-g)   (prefactors e^{alpha g}, e^{-alpha g^2})
    const float w = __fmaf_rn(lg2a(f1w), 0.6931471805599453f,
                              alpha * g * (1.0f - g));

    float* ob = out + (size_t)(b * 3 * PD) * PO + o;
    ob[(size_t)(d) * PO]          = __fdividef(f1y, f1w);  // y
    ob[(size_t)(PD + d) * PO]     = w;                     // logsumexp
    ob[(size_t)(2 * PD + d) * PO] = __fdividef(f2y, f2w);  // y_trans
}

extern "C" void kernel_launch(void* const* d_in, const int* in_sizes, int n_in,
                              void* d_out, int out_size) {
    const float* x    = (const float*)d_in[0];   // (8, 192, 512)
    const float* grid = (const float*)d_in[1];   // (8, 256)
    const float* kern = (const float*)d_in[2];   // (64,)
    float* out = (float*)d_out;                  // (8, 192, 256)

    interp_kernel<<<PB * PD * 2, THREADS>>>(x, grid, kern, out);
}

// round 15
// speedup vs baseline: 1.5945x; 1.5945x over previous
#include <cuda_runtime.h>
#include <cuda_bf16.h>
#include <math.h>

// B=8, D=64, T=512, O=256 (fixed by the reference)
#define PB 8
#define PD 64
#define PT 512
#define PO 256
#define NK 28              // branch-2 Taylor terms (center 0.5, |z*dt| <= 6.93)
#define NK1 10             // branch-1 Taylor terms (|z*dt| <= 0.693)
#define NS (NK + NK1)      // 38 packed (w,y) moment sums
#define T0 0.5f

typedef unsigned long long u64;

__device__ __forceinline__ float ex2a(float x) {
    float y; asm("ex2.approx.ftz.f32 %0, %1;" : "=f"(y) : "f"(x)); return y;
}
__device__ __forceinline__ float lg2a(float x) {
    float y; asm("lg2.approx.ftz.f32 %0, %1;" : "=f"(y) : "f"(x)); return y;
}
__device__ __forceinline__ u64 pk2(float lo, float hi) {
    u64 r; asm("mov.b64 %0, {%1, %2};" : "=l"(r) : "f"(lo), "f"(hi)); return r;
}
__device__ __forceinline__ void upk2(u64 v, float& lo, float& hi) {
    asm("mov.b64 {%0, %1}, %2;" : "=f"(lo), "=f"(hi) : "l"(v));
}
__device__ __forceinline__ u64 fma2(u64 a, u64 b, u64 c) {
    u64 d; asm("fma.rn.f32x2 %0, %1, %2, %3;" : "=l"(d) : "l"(a), "l"(b), "l"(c)); return d;
}
__device__ __forceinline__ u64 mul2(u64 a, u64 b) {
    u64 d; asm("mul.rn.f32x2 %0, %1, %2;" : "=l"(d) : "l"(a), "l"(b)); return d;
}
__device__ __forceinline__ u64 add2(u64 a, u64 b) {
    u64 d; asm("add.rn.f32x2 %0, %1, %2;" : "=l"(d) : "l"(a), "l"(b)); return d;
}

__constant__ float inv_fact[NK] = {
    1.0f,           1.0f,           5.0e-1f,        1.6666667e-1f,
    4.1666667e-2f,  8.3333333e-3f,  1.3888889e-3f,  1.9841270e-4f,
    2.4801587e-5f,  2.7557319e-6f,  2.7557319e-7f,  2.5052108e-8f,
    2.0876757e-9f,  1.6059044e-10f, 1.1470746e-11f, 7.6471637e-13f,
    4.7794773e-14f, 2.8114573e-15f, 1.5619207e-16f, 8.2206352e-18f,
    4.1103176e-19f, 1.9572941e-20f, 8.8967914e-22f, 3.8681702e-23f,
    1.6117376e-24f, 6.4469503e-26f, 2.4795963e-27f, 9.1836899e-29f
};

__global__ __launch_bounds__(PO, 4)
void interp_kernel(const float* __restrict__ x,
                   const float* __restrict__ grid,
                   const float* __restrict__ kern,
                   float* __restrict__ out) {
    // One block per (b, d): 256 threads, 8 warps.
    const int bd = blockIdx.x;
    const int b  = bd >> 6;
    const int d  = bd & (PD - 1);
    const int tid  = threadIdx.x;
    const int lane = tid & 31;
    const int wid  = tid >> 5;
    const int w    = wid & 3;         // k-chain offset (stride 4)
    const int tsel = wid >> 2;        // t-half this warp scans

    // sU viewed as ulonglong2: .x = (u1, u1*v), .y = (u2, u2*v)
    __shared__ __align__(16) float4 sPw[PT];       // {dt, dt2, dt4, dt8}
    __shared__ __align__(16) float4 sU[PT];
    __shared__ __align__(8)  u64 sPart[NS][66];    // per-(s, tsel*32+lane)
    __shared__ __align__(8)  float2 sM[NS];        // s<10: S1 k=s; else S2 k=s-10

    const float* vp = x + (size_t)(b * 3 * PD + d) * PT;
    const float* mp = vp + (size_t)PD * PT;
    const float* tp = vp + (size_t)(2 * PD) * PT;

    const float k0 = kern[d];
    const float alpha = (k0 > 20.0f) ? k0 : log1pf(__expf(k0));
    const float c1 = -alpha * 1.4426950408889634f;   // -alpha*log2(e)

    // ---- Phase A0: per-t weights + power ladder (mask is exactly 0/1) ----
    #pragma unroll
    for (int r = 0; r < 2; r++) {
        const int t = r * PO + tid;
        const float tv = tp[t];
        const float mv = mp[t];
        const float vv = vp[t];
        float u1 = ex2a(c1 * tv * tv);           // e^{-alpha t^2}
        if (mv < 0.5f) u1 = 0.0f;
        const float p2 = u1 * u1;
        const float p4 = p2 * p2;
        const float p8 = p4 * p4;
        const float u2 = p8 * p2;                // u1^10
        const float dt  = tv - T0;
        const float dt2 = dt * dt;
        const float dt4 = dt2 * dt2;
        sPw[t] = make_float4(dt, dt2, dt4, dt4 * dt4);
        sU[t]  = make_float4(u1, u1 * vv, u2, u2 * vv);
    }
    __syncthreads();

    // ---- Phase A: warp (w, tsel) owns k-chain {w, w+4, ..., w+24} over its
    //      t-half. Packed (w,y) sums: S1 ks {w, w+4, w+8<10}, S2 all 7. ----
    u64 a0=0,a1=0,a2=0,a3=0,a4=0,a5=0,a6=0;   // S2 k = w+4j
    u64 e0=0,e1=0,e2=0;                        // S1 k = w+4j (j<3)
    {
        const int tb = tsel * 256;
        #pragma unroll 2
        for (int c = 0; c < 8; c++) {
            const int t = tb + c * 32 + lane;
            const float4 P = sPw[t];
            const ulonglong2 UU = *(const ulonglong2*)(sU + t);
            float pw0s;
            if      (w == 0) pw0s = 1.0f;
            else if (w == 1) pw0s = P.x;
            else if (w == 2) pw0s = P.y;
            else             pw0s = P.x * P.y;
            const u64 P4 = pk2(P.z, P.z);
            u64 PW = pk2(pw0s, pw0s);
            e0 = fma2(UU.x, PW, e0);  a0 = fma2(UU.y, PW, a0);
            PW = mul2(PW, P4);
            e1 = fma2(UU.x, PW, e1);  a1 = fma2(UU.y, PW, a1);
            PW = mul2(PW, P4);
            if (w < 2) e2 = fma2(UU.x, PW, e2);
            a2 = fma2(UU.y, PW, a2);
            PW = mul2(PW, P4);  a3 = fma2(UU.y, PW, a3);
            PW = mul2(PW, P4);  a4 = fma2(UU.y, PW, a4);
            PW = mul2(PW, P4);  a5 = fma2(UU.y, PW, a5);
            PW = mul2(PW, P4);  a6 = fma2(UU.y, PW, a6);
        }
    }
    {
        const int col = tsel * 32 + lane;
        sPart[w][col]      = e0;
        sPart[w + 4][col]  = e1;
        if (w < 2) sPart[w + 8][col] = e2;
        sPart[10 + w][col]      = a0;
        sPart[10 + w + 4][col]  = a1;
        sPart[10 + w + 8][col]  = a2;
        sPart[10 + w + 12][col] = a3;
        sPart[10 + w + 16][col] = a4;
        sPart[10 + w + 20][col] = a5;
        sPart[10 + w + 24][col] = a6;
    }
    __syncthreads();

    // ---- Stage 2: 76 threads; thread (s, half) sums 32 lane-partials in
    //      fixed order (deterministic), then 38 threads fold halves + 1/k!.
    __shared__ __align__(8) u64 sQ[NS][2];
    if (tid < 2 * NS) {
        const int s = tid >> 1;
        const int hf = tid & 1;
        const u64* row = &sPart[s][hf * 32];
        u64 acc = 0;
        #pragma unroll 4
        for (int l = 0; l < 32; l++) acc = add2(acc, row[l]);
        sQ[s][hf] = acc;
    }
    __syncthreads();
    if (tid < NS) {
        const int s = tid;
        float lo, hi;
        upk2(add2(sQ[s][0], sQ[s][1]), lo, hi);
        const float f = inv_fact[(s < NK1) ? s : (s - NK1)];
        sM[s] = make_float2(lo * f, hi * f);
    }
    __syncthreads();

    // ---- Phase B: per-output packed Horner evaluation ----
    const int o = tid;
    const float g = grid[b * PO + o];
    const float z1 = 2.0f * alpha * g;       // beta1 * g
    const float z2 = 20.0f * alpha * g;      // beta2 * g
    const u64 Z1 = pk2(z1, z1);
    const u64 Z2 = pk2(z2, z2);

    u64 F2 = 0;
    #pragma unroll
    for (int k = NK - 1; k >= 0; k--)
        F2 = fma2(F2, Z2, *(const u64*)(sM + NK1 + k));
    u64 F1 = 0;
    #pragma unroll
    for (int k = NK1 - 1; k >= 0; k--)
        F1 = fma2(F1, Z1, *(const u64*)(sM + k));

    float f1w, f1y, f2w, f2y;
    upk2(F1, f1w, f1y);
    upk2(F2, f2w, f2y);

    // w = ln(S1w) + alpha*g*(1-g)   (prefactors e^{alpha g}, e^{-alpha g^2})
    const float wv = __fmaf_rn(lg2a(f1w), 0.6931471805599453f,
                               alpha * g * (1.0f - g));

    float* ob = out + (size_t)(b * 3 * PD) * PO + o;
    ob[(size_t)(d) * PO]          = __fdividef(f1y, f1w);  // y
    ob[(size_t)(PD + d) * PO]     = wv;                    // logsumexp
    ob[(size_t)(2 * PD + d) * PO] = __fdividef(f2y, f2w);  // y_trans
}

extern "C" void kernel_launch(void* const* d_in, const int* in_sizes, int n_in,
                              void* d_out, int out_size) {
    const float* x    = (const float*)d_in[0];   // (8, 192, 512)
    const float* grid = (const float*)d_in[1];   // (8, 256)
    const float* kern = (const float*)d_in[2];   // (64,)
    float* out = (float*)d_out;                  // (8, 192, 256)

    interp_kernel<<<PB * PD, PO>>>(x, grid, kern, out);
}

// round 16
// speedup vs baseline: 1.6631x; 1.0430x over previous
#include <cuda_runtime.h>
#include <cuda_bf16.h>
#include <math.h>

// B=8, D=64, T=512, O=256 (fixed by the reference)
#define PB 8
#define PD 64
#define PT 512
#define PO 256
#define NK 28              // branch-2 Taylor terms (center 0.5, |z*dt| <= 6.93)
#define NK1 10             // branch-1 Taylor terms (|z*dt| <= 0.693)
#define NS (NK + NK1)      // 38 packed (w,y) moment sums
#define T0 0.5f

typedef unsigned long long u64;

__device__ __forceinline__ float ex2a(float x) {
    float y; asm("ex2.approx.ftz.f32 %0, %1;" : "=f"(y) : "f"(x)); return y;
}
__device__ __forceinline__ float lg2a(float x) {
    float y; asm("lg2.approx.ftz.f32 %0, %1;" : "=f"(y) : "f"(x)); return y;
}
__device__ __forceinline__ u64 pk2(float lo, float hi) {
    u64 r; asm("mov.b64 %0, {%1, %2};" : "=l"(r) : "f"(lo), "f"(hi)); return r;
}
__device__ __forceinline__ void upk2(u64 v, float& lo, float& hi) {
    asm("mov.b64 {%0, %1}, %2;" : "=f"(lo), "=f"(hi) : "l"(v));
}
__device__ __forceinline__ u64 fma2(u64 a, u64 b, u64 c) {
    u64 d; asm("fma.rn.f32x2 %0, %1, %2, %3;" : "=l"(d) : "l"(a), "l"(b), "l"(c)); return d;
}
__device__ __forceinline__ u64 mul2(u64 a, u64 b) {
    u64 d; asm("mul.rn.f32x2 %0, %1, %2;" : "=l"(d) : "l"(a), "l"(b)); return d;
}
__device__ __forceinline__ u64 add2(u64 a, u64 b) {
    u64 d; asm("add.rn.f32x2 %0, %1, %2;" : "=l"(d) : "l"(a), "l"(b)); return d;
}

__constant__ float inv_fact[NK] = {
    1.0f,           1.0f,           5.0e-1f,        1.6666667e-1f,
    4.1666667e-2f,  8.3333333e-3f,  1.3888889e-3f,  1.9841270e-4f,
    2.4801587e-5f,  2.7557319e-6f,  2.7557319e-7f,  2.5052108e-8f,
    2.0876757e-9f,  1.6059044e-10f, 1.1470746e-11f, 7.6471637e-13f,
    4.7794773e-14f, 2.8114573e-15f, 1.5619207e-16f, 8.2206352e-18f,
    4.1103176e-19f, 1.9572941e-20f, 8.8967914e-22f, 3.8681702e-23f,
    1.6117376e-24f, 6.4469503e-26f, 2.4795963e-27f, 9.1836899e-29f
};

__global__ __launch_bounds__(PO, 4)
void interp_kernel(const float* __restrict__ x,
                   const float* __restrict__ grid,
                   const float* __restrict__ kern,
                   float* __restrict__ out) {
    // One block per (b, d): 256 threads, 8 warps.
    const int bd = blockIdx.x;
    const int b  = bd >> 6;
    const int d  = bd & (PD - 1);
    const int tid  = threadIdx.x;
    const int lane = tid & 31;
    const int wid  = tid >> 5;
    const int w    = wid & 3;         // k-chain offset (stride 4)
    const int tsel = wid >> 2;        // t-half this warp scans

    // sU viewed as ulonglong2: .x = (u1, u1*v), .y = (u2, u2*v)
    __shared__ __align__(16) float4 sPw[PT];       // {dt, dt2, dt4, dt8}
    __shared__ __align__(16) float4 sU[PT];
    __shared__ __align__(8)  u64 sPart[NS][66];    // per-(s, tsel*32+lane)
    __shared__ __align__(8)  float2 sM[NS];        // s<10: S1 k=s; else S2 k=s-10

    const float* vp = x + (size_t)(b * 3 * PD + d) * PT;
    const float* mp = vp + (size_t)PD * PT;
    const float* tp = vp + (size_t)(2 * PD) * PT;

    // ---- Prefetch both rounds of inputs (overlap L2 latency) ----
    const float tv0 = tp[tid];
    const float tv1 = tp[tid + PO];
    const float mv0 = mp[tid];
    const float mv1 = mp[tid + PO];
    const float vv0 = vp[tid];
    const float vv1 = vp[tid + PO];

    const float k0 = kern[d];
    const float alpha = (k0 > 20.0f) ? k0 : log1pf(__expf(k0));
    const float c1 = -alpha * 1.4426950408889634f;   // -alpha*log2(e)

    // ---- Phase A0: per-t weights + power ladder (mask is exactly 0/1) ----
    {
        float u1 = ex2a(c1 * tv0 * tv0);
        if (mv0 < 0.5f) u1 = 0.0f;
        const float p2 = u1 * u1, p4 = p2 * p2, p8 = p4 * p4;
        const float u2 = p8 * p2;
        const float dt = tv0 - T0, dt2 = dt * dt, dt4 = dt2 * dt2;
        sPw[tid] = make_float4(dt, dt2, dt4, dt4 * dt4);
        sU[tid]  = make_float4(u1, u1 * vv0, u2, u2 * vv0);
    }
    {
        float u1 = ex2a(c1 * tv1 * tv1);
        if (mv1 < 0.5f) u1 = 0.0f;
        const float p2 = u1 * u1, p4 = p2 * p2, p8 = p4 * p4;
        const float u2 = p8 * p2;
        const float dt = tv1 - T0, dt2 = dt * dt, dt4 = dt2 * dt2;
        sPw[tid + PO] = make_float4(dt, dt2, dt4, dt4 * dt4);
        sU[tid + PO]  = make_float4(u1, u1 * vv1, u2, u2 * vv1);
    }
    __syncthreads();

    // ---- Phase A: warp (w, tsel) owns k-chain {w, w+4, ..., w+24} over its
    //      t-half; even/odd sub-chains step by dt8 (depth 4, not 7). ----
    u64 a0=0,a1=0,a2=0,a3=0,a4=0,a5=0,a6=0;   // S2 k = w+4j
    u64 e0=0,e1=0,e2=0;                        // S1 k = w+4j (j<3)
    {
        const int tb = tsel * 256;
        #pragma unroll 2
        for (int c = 0; c < 8; c++) {
            const int t = tb + c * 32 + lane;
            const float4 P = sPw[t];
            const ulonglong2 UU = *(const ulonglong2*)(sU + t);
            float pw0s;
            if      (w == 0) pw0s = 1.0f;
            else if (w == 1) pw0s = P.x;
            else if (w == 2) pw0s = P.y;
            else             pw0s = P.x * P.y;
            const u64 P8 = pk2(P.w, P.w);
            u64 PWe = pk2(pw0s, pw0s);                 // j = 0, 2, 4, 6
            u64 PWo = pk2(pw0s * P.z, pw0s * P.z);     // j = 1, 3, 5
            e0 = fma2(UU.x, PWe, e0);  a0 = fma2(UU.y, PWe, a0);
            e1 = fma2(UU.x, PWo, e1);  a1 = fma2(UU.y, PWo, a1);
            PWe = mul2(PWe, P8);
            PWo = mul2(PWo, P8);
            if (w < 2) e2 = fma2(UU.x, PWe, e2);
            a2 = fma2(UU.y, PWe, a2);
            a3 = fma2(UU.y, PWo, a3);
            PWe = mul2(PWe, P8);
            PWo = mul2(PWo, P8);
            a4 = fma2(UU.y, PWe, a4);
            a5 = fma2(UU.y, PWo, a5);
            PWe = mul2(PWe, P8);
            a6 = fma2(UU.y, PWe, a6);
        }
    }
    {
        const int col = tsel * 32 + lane;
        sPart[w][col]      = e0;
        sPart[w + 4][col]  = e1;
        if (w < 2) sPart[w + 8][col] = e2;
        sPart[10 + w][col]      = a0;
        sPart[10 + w + 4][col]  = a1;
        sPart[10 + w + 8][col]  = a2;
        sPart[10 + w + 12][col] = a3;
        sPart[10 + w + 16][col] = a4;
        sPart[10 + w + 20][col] = a5;
        sPart[10 + w + 24][col] = a6;
    }
    __syncthreads();

    // ---- Stage 2 (single step): thread s sums 64 lane-partials in fixed
    //      order with 4 interleaved accumulators, applies 1/k!. ----
    if (tid < NS) {
        const u64* row = sPart[tid];
        u64 q0 = 0, q1 = 0, q2 = 0, q3 = 0;
        #pragma unroll 4
        for (int l = 0; l < 64; l += 4) {
            q0 = add2(q0, row[l]);
            q1 = add2(q1, row[l + 1]);
            q2 = add2(q2, row[l + 2]);
            q3 = add2(q3, row[l + 3]);
        }
        float lo, hi;
        upk2(add2(add2(q0, q1), add2(q2, q3)), lo, hi);
        const float f = inv_fact[(tid < NK1) ? tid : (tid - NK1)];
        sM[tid] = make_float2(lo * f, hi * f);
    }
    __syncthreads();

    // ---- Phase B: per-output packed Horner (even/odd split for S2) ----
    const int o = tid;
    const float g = grid[b * PO + o];
    const float z1 = 2.0f * alpha * g;       // beta1 * g
    const float z2 = 20.0f * alpha * g;      // beta2 * g
    const u64 Z1 = pk2(z1, z1);
    const u64 Z2sq = pk2(z2 * z2, z2 * z2);
    const u64 Z2 = pk2(z2, z2);

    // S2 = Fe(z2^2) + z2 * Fo(z2^2), NK = 28 -> 14 even + 14 odd terms.
    u64 Fe = 0, Fo = 0;
    #pragma unroll
    for (int j = 13; j >= 0; j--) {
        Fe = fma2(Fe, Z2sq, *(const u64*)(sM + NK1 + 2 * j));
        Fo = fma2(Fo, Z2sq, *(const u64*)(sM + NK1 + 2 * j + 1));
    }
    const u64 F2 = fma2(Fo, Z2, Fe);
    u64 F1 = 0;
    #pragma unroll
    for (int k = NK1 - 1; k >= 0; k--)
        F1 = fma2(F1, Z1, *(const u64*)(sM + k));

    float f1w, f1y, f2w, f2y;
    upk2(F1, f1w, f1y);
    upk2(F2, f2w, f2y);

    // w = ln(S1w) + alpha*g*(1-g)   (prefactors e^{alpha g}, e^{-alpha g^2})
    const float wv = __fmaf_rn(lg2a(f1w), 0.6931471805599453f,
                               alpha * g * (1.0f - g));

    float* ob = out + (size_t)(b * 3 * PD) * PO + o;
    ob[(size_t)(d) * PO]          = __fdividef(f1y, f1w);  // y
    ob[(size_t)(PD + d) * PO]     = wv;                    // logsumexp
    ob[(size_t)(2 * PD + d) * PO] = __fdividef(f2y, f2w);  // y_trans
}

extern "C" void kernel_launch(void* const* d_in, const int* in_sizes, int n_in,
                              void* d_out, int out_size) {
    const float* x    = (const float*)d_in[0];   // (8, 192, 512)
    const float* grid = (const float*)d_in[1];   // (8, 256)
    const float* kern = (const float*)d_in[2];   // (64,)
    float* out = (float*)d_out;                  // (8, 192, 256)

    interp_kernel<<<PB * PD, PO>>>(x, grid, kern, out);
}